// round 1
// baseline (speedup 1.0000x reference)
#include <cuda_runtime.h>

// ---------------------------------------------------------------------------
// GCN_63694364999884: 2-layer GCN + LoRA + log_softmax
// Inputs (metadata order):
//  0: x          [N,128]  f32
//  1: edge_index [2,E]    i32   (row 0 = src, row 1 = dst)
//  2: domain_idx [N]      i32
//  3: emb_table  [3,4096] f32
//  4: W1 [4224,32] 5: b1[32] 6: A1[32,8] 7: B1[8,32]
//  8: W2 [32,5]    9: b2[5] 10: A2[5,8]  11: B2[8,5]
// out: [N,5] f32 log_softmax
// ---------------------------------------------------------------------------

#define NMAX 50000
#define LORA_R 8

__device__ int   g_deg [NMAX];
__device__ float g_dis [NMAX];
__device__ float g_embW[3 * 32];
__device__ float g_hW1 [NMAX * 32];
__device__ float g_agg1[NMAX * 32];
__device__ float g_hW2 [NMAX * 5];
__device__ float g_agg2[NMAX * 5];

// ---------------------------------------------------------------------------
__global__ void k_zero_deg(int n) {
    int i = blockIdx.x * blockDim.x + threadIdx.x;
    if (i < n) g_deg[i] = 0;
}

__global__ void k_deg(const int* __restrict__ dst, int E) {
    int i = blockIdx.x * blockDim.x + threadIdx.x;
    if (i < E) atomicAdd(&g_deg[dst[i]], 1);
}

__global__ void k_dis(int n) {
    int i = blockIdx.x * blockDim.x + threadIdx.x;
    if (i < n) g_dis[i] = rsqrtf((float)g_deg[i] + 1.0f);
}

// embW[d][j] = sum_k emb[d][k] * W1[k][j]  (k < 4096), 3 blocks of 256 threads
__global__ void k_embW(const float* __restrict__ emb, const float* __restrict__ W1) {
    __shared__ float part[256];
    int d = blockIdx.x;
    int col = threadIdx.x & 31;
    int chunk = threadIdx.x >> 5;       // 0..7, each covers 512 k's
    float acc = 0.0f;
    int k0 = chunk * 512;
    const float* er = emb + d * 4096;
    for (int k = k0; k < k0 + 512; ++k)
        acc += er[k] * W1[k * 32 + col];
    part[threadIdx.x] = acc;
    __syncthreads();
    if (chunk == 0) {
        float s = 0.0f;
        #pragma unroll
        for (int c = 0; c < 8; ++c) s += part[c * 32 + col];
        g_embW[d * 32 + col] = s;
    }
}

// Per node: hW1 = embW[domain] + x @ W1[4096:,:]; agg1 init = dis^2*hW1 + b1
// 8 nodes per 256-thread block (32 threads -> 32 output cols per node).
__global__ void k_hW1(const float* __restrict__ x, const float* __restrict__ W1,
                      const float* __restrict__ b1, const int* __restrict__ dom, int n) {
    __shared__ float sW[128 * 32];   // 16 KB
    __shared__ float sx[8 * 128];    //  4 KB
    __shared__ float sE[96];
    __shared__ float sb[32];
    int tid = threadIdx.x;
    int base = blockIdx.x * 8;

    for (int t = tid; t < 128 * 32; t += 256)
        sW[t] = W1[4096 * 32 + t];
    for (int t = tid; t < 8 * 128; t += 256) {
        int ln = t >> 7, k = t & 127;
        int node = base + ln;
        sx[t] = (node < n) ? x[node * 128 + k] : 0.0f;
    }
    if (tid < 96) sE[tid] = g_embW[tid];
    if (tid < 32) sb[tid] = b1[tid];
    __syncthreads();

    int ln = tid >> 5, j = tid & 31;
    int node = base + ln;
    if (node < n) {
        float acc = 0.0f;
        #pragma unroll
        for (int k = 0; k < 128; ++k)
            acc = fmaf(sx[ln * 128 + k], sW[k * 32 + j], acc);
        float hw = acc + sE[dom[node] * 32 + j];
        g_hW1[node * 32 + j] = hw;
        float dis = g_dis[node];
        g_agg1[node * 32 + j] = dis * dis * hw + sb[j];
    }
}

// Edge aggregation layer 1: agg1[dst] += norm * hW1[src], 8 lanes/edge, float4 gather
__global__ void k_agg1(const int* __restrict__ src, const int* __restrict__ dst, int E) {
    int gid = blockIdx.x * blockDim.x + threadIdx.x;
    int e = gid >> 3;
    int q = gid & 7;
    if (e >= E) return;
    int s = src[e], d = dst[e];
    float norm = g_dis[s] * g_dis[d];
    const float4 v = *reinterpret_cast<const float4*>(&g_hW1[s * 32 + q * 4]);
    float* base = &g_agg1[d * 32 + q * 4];
    atomicAdd(base + 0, norm * v.x);
    atomicAdd(base + 1, norm * v.y);
    atomicAdd(base + 2, norm * v.z);
    atomicAdd(base + 3, norm * v.w);
}

// LoRA1 + ReLU + W2 + agg2 init, one thread per node
__global__ void k_mid(const float* __restrict__ A1, const float* __restrict__ B1,
                      const float* __restrict__ W2, const float* __restrict__ b2, int n) {
    __shared__ float sA1[32 * 8], sB1[8 * 32], sW2[32 * 5], sb2[5];
    int tid = threadIdx.x;
    if (tid < 256) { sA1[tid] = A1[tid]; sB1[tid] = B1[tid]; }
    if (tid < 160) sW2[tid] = W2[tid];
    if (tid < 5)   sb2[tid] = b2[tid];
    __syncthreads();

    int i = blockIdx.x * blockDim.x + tid;
    if (i >= n) return;

    float t[LORA_R];
    #pragma unroll
    for (int r = 0; r < LORA_R; ++r) t[r] = 0.0f;
    #pragma unroll
    for (int j = 0; j < 32; ++j) {
        float aj = g_agg1[i * 32 + j];
        #pragma unroll
        for (int r = 0; r < LORA_R; ++r)
            t[r] = fmaf(aj, sA1[j * LORA_R + r], t[r]);
    }
    float hw2[5] = {0, 0, 0, 0, 0};
    #pragma unroll
    for (int j = 0; j < 32; ++j) {
        float lv = 0.0f;
        #pragma unroll
        for (int r = 0; r < LORA_R; ++r)
            lv = fmaf(t[r], sB1[r * 32 + j], lv);
        lv *= (1.0f / LORA_R);
        lv = fmaxf(lv, 0.0f);            // relu
        #pragma unroll
        for (int c = 0; c < 5; ++c)
            hw2[c] = fmaf(lv, sW2[j * 5 + c], hw2[c]);
    }
    float dis = g_dis[i];
    float d2 = dis * dis;
    #pragma unroll
    for (int c = 0; c < 5; ++c) {
        g_hW2[i * 5 + c]  = hw2[c];
        g_agg2[i * 5 + c] = d2 * hw2[c] + sb2[c];
    }
}

// Edge aggregation layer 2 (dim 5), one thread per edge
__global__ void k_agg2(const int* __restrict__ src, const int* __restrict__ dst, int E) {
    int e = blockIdx.x * blockDim.x + threadIdx.x;
    if (e >= E) return;
    int s = src[e], d = dst[e];
    float norm = g_dis[s] * g_dis[d];
    #pragma unroll
    for (int c = 0; c < 5; ++c)
        atomicAdd(&g_agg2[d * 5 + c], norm * g_hW2[s * 5 + c]);
}

// LoRA2 + log_softmax, one thread per node
__global__ void k_final(const float* __restrict__ A2, const float* __restrict__ B2,
                        float* __restrict__ out, int n) {
    __shared__ float sA2[5 * 8], sB2[8 * 5];
    int tid = threadIdx.x;
    if (tid < 40) { sA2[tid] = A2[tid]; sB2[tid] = B2[tid]; }
    __syncthreads();

    int i = blockIdx.x * blockDim.x + tid;
    if (i >= n) return;

    float a[5];
    #pragma unroll
    for (int c = 0; c < 5; ++c) a[c] = g_agg2[i * 5 + c];

    float t[LORA_R];
    #pragma unroll
    for (int r = 0; r < LORA_R; ++r) {
        float s = 0.0f;
        #pragma unroll
        for (int c = 0; c < 5; ++c)
            s = fmaf(a[c], sA2[c * LORA_R + r], s);
        t[r] = s;
    }
    float l[5];
    float m = -1e30f;
    #pragma unroll
    for (int c = 0; c < 5; ++c) {
        float s = 0.0f;
        #pragma unroll
        for (int r = 0; r < LORA_R; ++r)
            s = fmaf(t[r], sB2[r * 5 + c], s);
        l[c] = s * (1.0f / LORA_R);
        m = fmaxf(m, l[c]);
    }
    float se = 0.0f;
    #pragma unroll
    for (int c = 0; c < 5; ++c) se += expf(l[c] - m);
    float lse = m + logf(se);
    #pragma unroll
    for (int c = 0; c < 5; ++c)
        out[i * 5 + c] = l[c] - lse;
}

// ---------------------------------------------------------------------------
extern "C" void kernel_launch(void* const* d_in, const int* in_sizes, int n_in,
                              void* d_out, int out_size) {
    const float* x    = (const float*)d_in[0];
    const int*   ei   = (const int*)  d_in[1];
    const int*   dom  = (const int*)  d_in[2];
    const float* emb  = (const float*)d_in[3];
    const float* W1   = (const float*)d_in[4];
    const float* b1   = (const float*)d_in[5];
    const float* A1   = (const float*)d_in[6];
    const float* B1   = (const float*)d_in[7];
    const float* W2   = (const float*)d_in[8];
    const float* b2   = (const float*)d_in[9];
    const float* A2   = (const float*)d_in[10];
    const float* B2   = (const float*)d_in[11];
    float* out = (float*)d_out;

    int N = in_sizes[2];            // domain_idx count = node count
    int E = in_sizes[1] / 2;        // edge_index is [2, E]
    const int* src = ei;
    const int* dst = ei + E;

    int nb256 = (N + 255) / 256;

    k_zero_deg<<<nb256, 256>>>(N);
    k_deg<<<(E + 255) / 256, 256>>>(dst, E);
    k_dis<<<nb256, 256>>>(N);
    k_embW<<<3, 256>>>(emb, W1);
    k_hW1<<<(N + 7) / 8, 256>>>(x, W1, b1, dom, N);
    {
        long long total = (long long)E * 8;
        int blocks = (int)((total + 255) / 256);
        k_agg1<<<blocks, 256>>>(src, dst, E);
    }
    k_mid<<<nb256, 256>>>(A1, B1, W2, b2, N);
    k_agg2<<<(E + 255) / 256, 256>>>(src, dst, E);
    k_final<<<nb256, 256>>>(A2, B2, out, N);
}

// round 2
// speedup vs baseline: 1.7993x; 1.7993x over previous
#include <cuda_runtime.h>

// ---------------------------------------------------------------------------
// GCN_63694364999884: 2-layer GCN + LoRA + log_softmax — CSR gather version
// ---------------------------------------------------------------------------

#define NMAX 50000
#define EMAX 1600000
#define LORA_R 8
#define SCAN_B 1024
#define NSCANB ((NMAX + SCAN_B - 1) / SCAN_B)   // 49

__device__ int   g_deg [NMAX];
__device__ int   g_off [NMAX];
__device__ int   g_cur [NMAX];
__device__ int   g_bsum[NSCANB];
__device__ int   g_bpre[NSCANB];
__device__ float g_dis [NMAX];
__device__ float g_embW[3 * 32];
__device__ float g_hW1 [NMAX * 32];
__device__ float g_agg1[NMAX * 32];
__device__ float g_hW2p[NMAX * 8];          // padded to 8 (cols 5..7 = 0)
__device__ int   g_eSrc[EMAX];
__device__ float g_eNorm[EMAX];

// ---------------------------------------------------------------------------
__global__ void k_zero(int n) {
    int i = blockIdx.x * blockDim.x + threadIdx.x;
    if (i < n) g_deg[i] = 0;
    if (i < 96) g_embW[i] = 0.0f;
}

__global__ void k_deg(const int* __restrict__ dst, int E) {
    int i = blockIdx.x * blockDim.x + threadIdx.x;
    if (i < E) atomicAdd(&g_deg[dst[i]], 1);
}

__global__ void k_dis(int n) {
    int i = blockIdx.x * blockDim.x + threadIdx.x;
    if (i < n) g_dis[i] = rsqrtf((float)g_deg[i] + 1.0f);
}

// ---- exclusive scan of g_deg -> g_off (3 kernels) -------------------------
__global__ void k_scan_block(int n) {
    __shared__ int sm[SCAN_B];
    int i = blockIdx.x * SCAN_B + threadIdx.x;
    int v = (i < n) ? g_deg[i] : 0;
    sm[threadIdx.x] = v;
    __syncthreads();
    #pragma unroll
    for (int o = 1; o < SCAN_B; o <<= 1) {
        int t = (threadIdx.x >= o) ? sm[threadIdx.x - o] : 0;
        __syncthreads();
        sm[threadIdx.x] += t;
        __syncthreads();
    }
    int incl = sm[threadIdx.x];
    if (i < n) g_off[i] = incl - v;
    if (threadIdx.x == SCAN_B - 1) g_bsum[blockIdx.x] = incl;
}

__global__ void k_scan_tops() {
    if (threadIdx.x == 0) {
        int r = 0;
        #pragma unroll
        for (int b = 0; b < NSCANB; ++b) { g_bpre[b] = r; r += g_bsum[b]; }
    }
}

__global__ void k_scan_add(int n) {
    int i = blockIdx.x * SCAN_B + threadIdx.x;
    if (i < n) {
        int o = g_off[i] + g_bpre[blockIdx.x];
        g_off[i] = o;
        g_cur[i] = o;
    }
}

// ---- scatter edges into per-dst buckets -----------------------------------
__global__ void k_scatter(const int* __restrict__ src, const int* __restrict__ dst, int E) {
    int e = blockIdx.x * blockDim.x + threadIdx.x;
    if (e >= E) return;
    int s = src[e], d = dst[e];
    int pos = atomicAdd(&g_cur[d], 1);
    g_eSrc[pos]  = s;
    g_eNorm[pos] = g_dis[s] * g_dis[d];
}

// ---- embW[d][j] = sum_k emb[d][k]*W1[k][j], k<4096; 32 blocks over k-chunks
__global__ void k_embW(const float* __restrict__ emb, const float* __restrict__ W1) {
    __shared__ float part[8][3][32];
    int col = threadIdx.x & 31;
    int w   = threadIdx.x >> 5;            // warp 0..7
    int k0  = blockIdx.x * 128 + w * 16;   // 16 k's per warp
    float a0 = 0.f, a1 = 0.f, a2 = 0.f;
    for (int i = 0; i < 16; ++i) {
        int k = k0 + i;
        float wv = W1[k * 32 + col];
        a0 = fmaf(emb[k],           wv, a0);
        a1 = fmaf(emb[4096 + k],    wv, a1);
        a2 = fmaf(emb[8192 + k],    wv, a2);
    }
    part[w][0][col] = a0; part[w][1][col] = a1; part[w][2][col] = a2;
    __syncthreads();
    if (threadIdx.x < 96) {
        int d = threadIdx.x >> 5, c = threadIdx.x & 31;
        float s = 0.f;
        #pragma unroll
        for (int ww = 0; ww < 8; ++ww) s += part[ww][d][c];
        atomicAdd(&g_embW[d * 32 + c], s);
    }
}

// ---- hW1 = embW[dom] + x @ W1[4096:,:]; 16 nodes per 512-thread block ------
__global__ void __launch_bounds__(512) k_hW1(const float* __restrict__ x,
                                             const float* __restrict__ W1,
                                             const int* __restrict__ dom, int n) {
    __shared__ float sW[128 * 32];   // 16 KB
    __shared__ float sx[16 * 128];   //  8 KB
    __shared__ float sE[96];
    int tid = threadIdx.x;
    int base = blockIdx.x * 16;

    {   // W1 tail: 4096 floats = 1024 float4, 2 per thread
        const float4* W4 = reinterpret_cast<const float4*>(W1 + 4096 * 32);
        float4* sW4 = reinterpret_cast<float4*>(sW);
        sW4[tid]       = W4[tid];
        sW4[tid + 512] = W4[tid + 512];
    }
    {   // x: 16 rows x 32 float4 = 512 float4, 1 per thread
        int ln = tid >> 5, f4 = tid & 31;
        int node = base + ln;
        float4 v = (node < n)
            ? reinterpret_cast<const float4*>(x)[node * 32 + f4]
            : make_float4(0.f, 0.f, 0.f, 0.f);
        reinterpret_cast<float4*>(sx)[ln * 32 + f4] = v;
    }
    if (tid < 96) sE[tid] = g_embW[tid];
    __syncthreads();

    int ln = tid >> 5, j = tid & 31;
    int node = base + ln;
    if (node < n) {
        float acc = 0.0f;
        #pragma unroll
        for (int k = 0; k < 128; ++k)
            acc = fmaf(sx[ln * 128 + k], sW[k * 32 + j], acc);
        g_hW1[node * 32 + j] = acc + sE[dom[node] * 32 + j];
    }
}

// ---- layer-1 aggregation: CSR gather, 8 threads/node, float4 ---------------
__global__ void k_agg1(const float* __restrict__ b1, int n) {
    int tid = threadIdx.x;
    int node = blockIdx.x * 32 + (tid >> 3);
    int q = tid & 7;
    if (node >= n) return;
    int off = g_off[node];
    int end = off + g_deg[node];
    float4 acc = make_float4(0.f, 0.f, 0.f, 0.f);
    int e = off;
    // unroll-2 for MLP
    for (; e + 2 <= end; e += 2) {
        int s0 = g_eSrc[e],     s1 = g_eSrc[e + 1];
        float m0 = g_eNorm[e],  m1 = g_eNorm[e + 1];
        float4 v0 = *reinterpret_cast<const float4*>(&g_hW1[s0 * 32 + q * 4]);
        float4 v1 = *reinterpret_cast<const float4*>(&g_hW1[s1 * 32 + q * 4]);
        acc.x = fmaf(m0, v0.x, acc.x); acc.y = fmaf(m0, v0.y, acc.y);
        acc.z = fmaf(m0, v0.z, acc.z); acc.w = fmaf(m0, v0.w, acc.w);
        acc.x = fmaf(m1, v1.x, acc.x); acc.y = fmaf(m1, v1.y, acc.y);
        acc.z = fmaf(m1, v1.z, acc.z); acc.w = fmaf(m1, v1.w, acc.w);
    }
    if (e < end) {
        int s = g_eSrc[e]; float m = g_eNorm[e];
        float4 v = *reinterpret_cast<const float4*>(&g_hW1[s * 32 + q * 4]);
        acc.x = fmaf(m, v.x, acc.x); acc.y = fmaf(m, v.y, acc.y);
        acc.z = fmaf(m, v.z, acc.z); acc.w = fmaf(m, v.w, acc.w);
    }
    float dis = g_dis[node];
    float d2 = dis * dis;
    float4 h = *reinterpret_cast<const float4*>(&g_hW1[node * 32 + q * 4]);
    float4 r;
    r.x = acc.x + d2 * h.x + __ldg(&b1[q * 4 + 0]);
    r.y = acc.y + d2 * h.y + __ldg(&b1[q * 4 + 1]);
    r.z = acc.z + d2 * h.z + __ldg(&b1[q * 4 + 2]);
    r.w = acc.w + d2 * h.w + __ldg(&b1[q * 4 + 3]);
    *reinterpret_cast<float4*>(&g_agg1[node * 32 + q * 4]) = r;
}

// ---- LoRA1 + ReLU + W2 -> padded hW2 ---------------------------------------
__global__ void k_mid(const float* __restrict__ A1, const float* __restrict__ B1,
                      const float* __restrict__ W2, int n) {
    __shared__ float sA1[32 * 8], sB1[8 * 32], sW2[32 * 5];
    int tid = threadIdx.x;
    if (tid < 256) { sA1[tid] = A1[tid]; sB1[tid] = B1[tid]; }
    if (tid < 160) sW2[tid] = W2[tid];
    __syncthreads();

    int i = blockIdx.x * blockDim.x + tid;
    if (i >= n) return;

    float t[LORA_R];
    #pragma unroll
    for (int r = 0; r < LORA_R; ++r) t[r] = 0.0f;
    #pragma unroll
    for (int j = 0; j < 32; ++j) {
        float aj = g_agg1[i * 32 + j];
        #pragma unroll
        for (int r = 0; r < LORA_R; ++r)
            t[r] = fmaf(aj, sA1[j * LORA_R + r], t[r]);
    }
    float hw2[5] = {0, 0, 0, 0, 0};
    #pragma unroll
    for (int j = 0; j < 32; ++j) {
        float lv = 0.0f;
        #pragma unroll
        for (int r = 0; r < LORA_R; ++r)
            lv = fmaf(t[r], sB1[r * 32 + j], lv);
        lv *= (1.0f / LORA_R);
        lv = fmaxf(lv, 0.0f);
        #pragma unroll
        for (int c = 0; c < 5; ++c)
            hw2[c] = fmaf(lv, sW2[j * 5 + c], hw2[c]);
    }
    float4 lo = make_float4(hw2[0], hw2[1], hw2[2], hw2[3]);
    float4 hi = make_float4(hw2[4], 0.f, 0.f, 0.f);
    *reinterpret_cast<float4*>(&g_hW2p[i * 8 + 0]) = lo;
    *reinterpret_cast<float4*>(&g_hW2p[i * 8 + 4]) = hi;
}

// ---- layer-2 aggregation + LoRA2 + log_softmax, fused ----------------------
__global__ void k_out(const float* __restrict__ A2, const float* __restrict__ B2,
                      const float* __restrict__ b2, float* __restrict__ out, int n) {
    __shared__ float sA2[40], sB2[40], sb2[8];
    int tid = threadIdx.x;
    if (tid < 40) { sA2[tid] = A2[tid]; sB2[tid] = B2[tid]; }
    if (tid < 8)  sb2[tid] = (tid < 5) ? b2[tid] : 0.0f;
    __syncthreads();

    int node = blockIdx.x * 128 + (tid >> 1);
    int q = tid & 1;

    float4 acc = make_float4(0.f, 0.f, 0.f, 0.f);
    if (node < n) {
        int off = g_off[node];
        int end = off + g_deg[node];
        int e = off;
        for (; e + 2 <= end; e += 2) {
            int s0 = g_eSrc[e],    s1 = g_eSrc[e + 1];
            float m0 = g_eNorm[e], m1 = g_eNorm[e + 1];
            float4 v0 = *reinterpret_cast<const float4*>(&g_hW2p[s0 * 8 + q * 4]);
            float4 v1 = *reinterpret_cast<const float4*>(&g_hW2p[s1 * 8 + q * 4]);
            acc.x = fmaf(m0, v0.x, acc.x); acc.y = fmaf(m0, v0.y, acc.y);
            acc.z = fmaf(m0, v0.z, acc.z); acc.w = fmaf(m0, v0.w, acc.w);
            acc.x = fmaf(m1, v1.x, acc.x); acc.y = fmaf(m1, v1.y, acc.y);
            acc.z = fmaf(m1, v1.z, acc.z); acc.w = fmaf(m1, v1.w, acc.w);
        }
        if (e < end) {
            int s = g_eSrc[e]; float m = g_eNorm[e];
            float4 v = *reinterpret_cast<const float4*>(&g_hW2p[s * 8 + q * 4]);
            acc.x = fmaf(m, v.x, acc.x); acc.y = fmaf(m, v.y, acc.y);
            acc.z = fmaf(m, v.z, acc.z); acc.w = fmaf(m, v.w, acc.w);
        }
        float dis = g_dis[node];
        float d2 = dis * dis;
        float4 h = *reinterpret_cast<const float4*>(&g_hW2p[node * 8 + q * 4]);
        acc.x += d2 * h.x + sb2[q * 4 + 0];
        acc.y += d2 * h.y + sb2[q * 4 + 1];
        acc.z += d2 * h.z + sb2[q * 4 + 2];
        acc.w += d2 * h.w + sb2[q * 4 + 3];
    }
    // bring col 4 (odd lane's acc.x) to the even lane
    float c4 = __shfl_down_sync(0xFFFFFFFFu, acc.x, 1);
    if (node < n && q == 0) {
        float a[5] = {acc.x, acc.y, acc.z, acc.w, c4};
        float t[LORA_R];
        #pragma unroll
        for (int r = 0; r < LORA_R; ++r) {
            float s = 0.0f;
            #pragma unroll
            for (int c = 0; c < 5; ++c)
                s = fmaf(a[c], sA2[c * LORA_R + r], s);
            t[r] = s;
        }
        float l[5];
        float m = -1e30f;
        #pragma unroll
        for (int c = 0; c < 5; ++c) {
            float s = 0.0f;
            #pragma unroll
            for (int r = 0; r < LORA_R; ++r)
                s = fmaf(t[r], sB2[r * 5 + c], s);
            l[c] = s * (1.0f / LORA_R);
            m = fmaxf(m, l[c]);
        }
        float se = 0.0f;
        #pragma unroll
        for (int c = 0; c < 5; ++c) se += expf(l[c] - m);
        float lse = m + logf(se);
        #pragma unroll
        for (int c = 0; c < 5; ++c)
            out[node * 5 + c] = l[c] - lse;
    }
}

// ---------------------------------------------------------------------------
extern "C" void kernel_launch(void* const* d_in, const int* in_sizes, int n_in,
                              void* d_out, int out_size) {
    const float* x    = (const float*)d_in[0];
    const int*   ei   = (const int*)  d_in[1];
    const int*   dom  = (const int*)  d_in[2];
    const float* emb  = (const float*)d_in[3];
    const float* W1   = (const float*)d_in[4];
    const float* b1   = (const float*)d_in[5];
    const float* A1   = (const float*)d_in[6];
    const float* B1   = (const float*)d_in[7];
    const float* W2   = (const float*)d_in[8];
    const float* b2   = (const float*)d_in[9];
    const float* A2   = (const float*)d_in[10];
    const float* B2   = (const float*)d_in[11];
    float* out = (float*)d_out;

    int N = in_sizes[2];
    int E = in_sizes[1] / 2;
    const int* src = ei;
    const int* dst = ei + E;

    int nb256 = (N + 255) / 256;
    int eb256 = (E + 255) / 256;
    int nbScan = (N + SCAN_B - 1) / SCAN_B;

    k_zero<<<nb256, 256>>>(N);
    k_deg<<<eb256, 256>>>(dst, E);
    k_dis<<<nb256, 256>>>(N);
    k_scan_block<<<nbScan, SCAN_B>>>(N);
    k_scan_tops<<<1, 32>>>();
    k_scan_add<<<nbScan, SCAN_B>>>(N);
    k_scatter<<<eb256, 256>>>(src, dst, E);
    k_embW<<<32, 256>>>(emb, W1);
    k_hW1<<<(N + 15) / 16, 512>>>(x, W1, dom, N);
    k_agg1<<<(N + 31) / 32, 256>>>(b1, N);
    k_mid<<<nb256, 256>>>(A1, B1, W2, N);
    k_out<<<(N + 127) / 128, 256>>>(A2, B2, b2, out, N);
}

// round 3
// speedup vs baseline: 2.7334x; 1.5191x over previous
#include <cuda_runtime.h>

// ---------------------------------------------------------------------------
// GCN_63694364999884 — rank-8 transformed aggregation (LoRA commuted through
// the linear scatter-gather), CSR gather, fused epilogues.
// ---------------------------------------------------------------------------

#define NMAX 50000
#define EMAX 1600000
#define SCAN_B 1024
#define NSCANB ((NMAX + SCAN_B - 1) / SCAN_B)   // 49

__device__ int   g_deg [NMAX];
__device__ int   g_off [NMAX];
__device__ int   g_cur [NMAX];
__device__ int   g_bsum[NSCANB];
__device__ int   g_bpre[NSCANB];
__device__ float g_dis [NMAX];
__device__ float g_embW[3 * 32];
__device__ __align__(16) float g_W1A [128 * 8];   // W1[4096:].T-proj through A1
__device__ __align__(16) float g_embWA[3 * 8];    // embW @ A1
__device__ __align__(16) float g_cA1[8];          // b1 @ A1
__device__ __align__(16) float g_cA2[8];          // b2 @ A2
__device__ __align__(16) float g_t1[NMAX * 8];    // (x@W1A + embWA[dom])
__device__ __align__(16) float g_t2[NMAX * 8];    // hW2 @ A2
__device__ __align__(8)  int2  g_edge[EMAX];      // {src, norm} bucketed by dst

// ---------------------------------------------------------------------------
__global__ void k_zero(int n) {
    int i = blockIdx.x * blockDim.x + threadIdx.x;
    if (i < n) g_deg[i] = 0;
    if (i < 96) g_embW[i] = 0.0f;
}

// blocks [0,32): embW chunks; blocks [32,...): degree count
__global__ void k_deg_embW(const int* __restrict__ dst,
                           const float* __restrict__ emb,
                           const float* __restrict__ W1, int E) {
    if (blockIdx.x < 32) {
        __shared__ float part[8][3][32];
        int col = threadIdx.x & 31;
        int w   = threadIdx.x >> 5;
        int k0  = blockIdx.x * 128 + w * 16;
        float a0 = 0.f, a1 = 0.f, a2 = 0.f;
        #pragma unroll 4
        for (int i = 0; i < 16; ++i) {
            int k = k0 + i;
            float wv = W1[k * 32 + col];
            a0 = fmaf(emb[k],        wv, a0);
            a1 = fmaf(emb[4096 + k], wv, a1);
            a2 = fmaf(emb[8192 + k], wv, a2);
        }
        part[w][0][col] = a0; part[w][1][col] = a1; part[w][2][col] = a2;
        __syncthreads();
        if (threadIdx.x < 96) {
            int d = threadIdx.x >> 5, c = threadIdx.x & 31;
            float s = 0.f;
            #pragma unroll
            for (int ww = 0; ww < 8; ++ww) s += part[ww][d][c];
            atomicAdd(&g_embW[d * 32 + c], s);
        }
    } else {
        int e = (blockIdx.x - 32) * blockDim.x + threadIdx.x;
        if (e < E) atomicAdd(&g_deg[dst[e]], 1);
    }
}

// ---- scan pass 1: per-block exclusive scan (warp shuffles) + dis -----------
__global__ void __launch_bounds__(SCAN_B) k_scan1(int n) {
    __shared__ int wsum[32];
    int i = blockIdx.x * SCAN_B + threadIdx.x;
    int lane = threadIdx.x & 31, w = threadIdx.x >> 5;
    int v = (i < n) ? g_deg[i] : 0;
    if (i < n) g_dis[i] = rsqrtf((float)v + 1.0f);
    int s = v;
    #pragma unroll
    for (int o = 1; o < 32; o <<= 1) {
        int t = __shfl_up_sync(0xFFFFFFFFu, s, o);
        if (lane >= o) s += t;
    }
    if (lane == 31) wsum[w] = s;
    __syncthreads();
    if (w == 0) {
        int ws = wsum[lane];
        #pragma unroll
        for (int o = 1; o < 32; o <<= 1) {
            int t = __shfl_up_sync(0xFFFFFFFFu, ws, o);
            if (lane >= o) ws += t;
        }
        wsum[lane] = ws;
    }
    __syncthreads();
    int pre = (w > 0) ? wsum[w - 1] : 0;
    int incl = s + pre;
    if (i < n) g_off[i] = incl - v;
    if (threadIdx.x == SCAN_B - 1) g_bsum[blockIdx.x] = incl;
}

// ---- scan pass 2: scan 49 block sums with one warp --------------------------
__global__ void k_scan2() {
    int l = threadIdx.x;
    int v0 = (l < NSCANB) ? g_bsum[l] : 0;
    int v1 = (32 + l < NSCANB) ? g_bsum[32 + l] : 0;
    int s0 = v0, s1 = v1;
    #pragma unroll
    for (int o = 1; o < 32; o <<= 1) {
        int t0 = __shfl_up_sync(0xFFFFFFFFu, s0, o);
        int t1 = __shfl_up_sync(0xFFFFFFFFu, s1, o);
        if (l >= o) { s0 += t0; s1 += t1; }
    }
    int tot0 = __shfl_sync(0xFFFFFFFFu, s0, 31);
    if (l < NSCANB) g_bpre[l] = s0 - v0;
    if (32 + l < NSCANB) g_bpre[32 + l] = s1 - v1 + tot0;
}

__global__ void __launch_bounds__(SCAN_B) k_scan3(int n) {
    int i = blockIdx.x * SCAN_B + threadIdx.x;
    if (i < n) {
        int o = g_off[i] + g_bpre[blockIdx.x];
        g_off[i] = o;
        g_cur[i] = o;
    }
}

// ---- scatter edges (packed src+norm) into per-dst buckets -------------------
__global__ void k_scatter(const int* __restrict__ src, const int* __restrict__ dst, int E) {
    int e = blockIdx.x * blockDim.x + threadIdx.x;
    if (e >= E) return;
    int s = src[e], d = dst[e];
    int pos = atomicAdd(&g_cur[d], 1);
    float norm = g_dis[s] * g_dis[d];
    g_edge[pos] = make_int2(s, __float_as_int(norm));
}

// ---- precompute W1A = W1tail@A1, embWA = embW@A1, cA1 = b1@A1, cA2 = b2@A2 --
__global__ void __launch_bounds__(1024) k_prep(const float* __restrict__ W1,
                                               const float* __restrict__ A1,
                                               const float* __restrict__ b1,
                                               const float* __restrict__ A2,
                                               const float* __restrict__ b2) {
    __shared__ float sA1[256];
    int tid = threadIdx.x;
    if (tid < 256) sA1[tid] = A1[tid];
    __syncthreads();
    {   // W1A[k][r]
        int k = tid >> 3, r = tid & 7;
        float acc = 0.f;
        #pragma unroll
        for (int j = 0; j < 32; ++j)
            acc = fmaf(W1[(4096 + k) * 32 + j], sA1[j * 8 + r], acc);
        g_W1A[tid] = acc;
    }
    if (tid < 24) {
        int d = tid >> 3, r = tid & 7;
        float acc = 0.f;
        #pragma unroll
        for (int j = 0; j < 32; ++j)
            acc = fmaf(g_embW[d * 32 + j], sA1[j * 8 + r], acc);
        g_embWA[tid] = acc;
    } else if (tid < 32) {
        int r = tid - 24;
        float acc = 0.f;
        #pragma unroll
        for (int j = 0; j < 32; ++j)
            acc = fmaf(b1[j], sA1[j * 8 + r], acc);
        g_cA1[r] = acc;
    } else if (tid < 40) {
        int r = tid - 32;
        float acc = 0.f;
        #pragma unroll
        for (int c = 0; c < 5; ++c)
            acc = fmaf(b2[c], A2[c * 8 + r], acc);
        g_cA2[r] = acc;
    }
}

// ---- t1 = x @ W1A + embWA[dom]; 1 thread per node ---------------------------
__global__ void __launch_bounds__(256) k_t1(const float* __restrict__ x,
                                            const int* __restrict__ dom, int n) {
    __shared__ float4 sW[256];   // W1A as [k][2 float4]
    __shared__ float  sE[24];
    int tid = threadIdx.x;
    sW[tid] = reinterpret_cast<const float4*>(g_W1A)[tid];
    if (tid < 24) sE[tid] = g_embWA[tid];
    __syncthreads();

    int node = blockIdx.x * 256 + tid;
    if (node >= n) return;

    int d = dom[node] * 8;
    float4 a03 = make_float4(sE[d + 0], sE[d + 1], sE[d + 2], sE[d + 3]);
    float4 a47 = make_float4(sE[d + 4], sE[d + 5], sE[d + 6], sE[d + 7]);

    const float4* x4 = reinterpret_cast<const float4*>(x) + node * 32;
    #pragma unroll 4
    for (int k4 = 0; k4 < 32; ++k4) {
        float4 xv = x4[k4];
        #pragma unroll
        for (int c = 0; c < 4; ++c) {
            int k = k4 * 4 + c;
            float xc = (c == 0) ? xv.x : (c == 1) ? xv.y : (c == 2) ? xv.z : xv.w;
            float4 wlo = sW[2 * k], whi = sW[2 * k + 1];
            a03.x = fmaf(xc, wlo.x, a03.x); a03.y = fmaf(xc, wlo.y, a03.y);
            a03.z = fmaf(xc, wlo.z, a03.z); a03.w = fmaf(xc, wlo.w, a03.w);
            a47.x = fmaf(xc, whi.x, a47.x); a47.y = fmaf(xc, whi.y, a47.y);
            a47.z = fmaf(xc, whi.z, a47.z); a47.w = fmaf(xc, whi.w, a47.w);
        }
    }
    float4* t1 = reinterpret_cast<float4*>(g_t1) + node * 2;
    t1[0] = a03;
    t1[1] = a47;
}

// ---- layer-1 gather (8-dim) + LoRA1 + ReLU + W2 + A2, fused -----------------
__global__ void __launch_bounds__(256) k_agg1mid(const float* __restrict__ B1,
                                                 const float* __restrict__ W2,
                                                 const float* __restrict__ A2, int n) {
    __shared__ float sB1[256], sW2[160], sA2[40], sC[8];
    int tid = threadIdx.x;
    if (tid < 256) sB1[tid] = B1[tid];
    if (tid < 160) sW2[tid] = W2[tid];
    if (tid < 40)  sA2[tid] = A2[tid];
    if (tid < 8)   sC[tid]  = g_cA1[tid];
    __syncthreads();

    int node = blockIdx.x * 128 + (tid >> 1);
    int q = tid & 1;
    float4 acc = make_float4(0.f, 0.f, 0.f, 0.f);
    if (node < n) {
        int off = g_off[node];
        int end = off + g_deg[node];
        int e = off;
        for (; e + 2 <= end; e += 2) {
            int2 e0 = g_edge[e], e1 = g_edge[e + 1];
            float m0 = __int_as_float(e0.y), m1 = __int_as_float(e1.y);
            float4 v0 = *reinterpret_cast<const float4*>(&g_t1[e0.x * 8 + q * 4]);
            float4 v1 = *reinterpret_cast<const float4*>(&g_t1[e1.x * 8 + q * 4]);
            acc.x = fmaf(m0, v0.x, acc.x); acc.y = fmaf(m0, v0.y, acc.y);
            acc.z = fmaf(m0, v0.z, acc.z); acc.w = fmaf(m0, v0.w, acc.w);
            acc.x = fmaf(m1, v1.x, acc.x); acc.y = fmaf(m1, v1.y, acc.y);
            acc.z = fmaf(m1, v1.z, acc.z); acc.w = fmaf(m1, v1.w, acc.w);
        }
        if (e < end) {
            int2 e0 = g_edge[e];
            float m = __int_as_float(e0.y);
            float4 v = *reinterpret_cast<const float4*>(&g_t1[e0.x * 8 + q * 4]);
            acc.x = fmaf(m, v.x, acc.x); acc.y = fmaf(m, v.y, acc.y);
            acc.z = fmaf(m, v.z, acc.z); acc.w = fmaf(m, v.w, acc.w);
        }
        float dis = g_dis[node];
        float d2 = dis * dis;
        float4 h = *reinterpret_cast<const float4*>(&g_t1[node * 8 + q * 4]);
        acc.x += d2 * h.x + sC[q * 4 + 0];
        acc.y += d2 * h.y + sC[q * 4 + 1];
        acc.z += d2 * h.z + sC[q * 4 + 2];
        acc.w += d2 * h.w + sC[q * 4 + 3];
    }
    // exchange halves: lane q=0 collects q=1's float4
    float4 o;
    o.x = __shfl_xor_sync(0xFFFFFFFFu, acc.x, 1);
    o.y = __shfl_xor_sync(0xFFFFFFFFu, acc.y, 1);
    o.z = __shfl_xor_sync(0xFFFFFFFFu, acc.z, 1);
    o.w = __shfl_xor_sync(0xFFFFFFFFu, acc.w, 1);
    if (node < n && q == 0) {
        float a[8] = {acc.x, acc.y, acc.z, acc.w, o.x, o.y, o.z, o.w};
        float hw2[5] = {0, 0, 0, 0, 0};
        #pragma unroll
        for (int j = 0; j < 32; ++j) {
            float lv = 0.0f;
            #pragma unroll
            for (int r = 0; r < 8; ++r)
                lv = fmaf(a[r], sB1[r * 32 + j], lv);
            lv *= 0.125f;
            lv = fmaxf(lv, 0.0f);
            #pragma unroll
            for (int c = 0; c < 5; ++c)
                hw2[c] = fmaf(lv, sW2[j * 5 + c], hw2[c]);
        }
        float t2[8];
        #pragma unroll
        for (int r = 0; r < 8; ++r) {
            float s = 0.0f;
            #pragma unroll
            for (int c = 0; c < 5; ++c)
                s = fmaf(hw2[c], sA2[c * 8 + r], s);
            t2[r] = s;
        }
        float4* p = reinterpret_cast<float4*>(g_t2) + node * 2;
        p[0] = make_float4(t2[0], t2[1], t2[2], t2[3]);
        p[1] = make_float4(t2[4], t2[5], t2[6], t2[7]);
    }
}

// ---- layer-2 gather (8-dim) + LoRA2-B + log_softmax, fused ------------------
__global__ void __launch_bounds__(256) k_out(const float* __restrict__ B2,
                                             float* __restrict__ out, int n) {
    __shared__ float sB2[40], sC[8];
    int tid = threadIdx.x;
    if (tid < 40) sB2[tid] = B2[tid];
    if (tid < 8)  sC[tid]  = g_cA2[tid];
    __syncthreads();

    int node = blockIdx.x * 128 + (tid >> 1);
    int q = tid & 1;
    float4 acc = make_float4(0.f, 0.f, 0.f, 0.f);
    if (node < n) {
        int off = g_off[node];
        int end = off + g_deg[node];
        int e = off;
        for (; e + 2 <= end; e += 2) {
            int2 e0 = g_edge[e], e1 = g_edge[e + 1];
            float m0 = __int_as_float(e0.y), m1 = __int_as_float(e1.y);
            float4 v0 = *reinterpret_cast<const float4*>(&g_t2[e0.x * 8 + q * 4]);
            float4 v1 = *reinterpret_cast<const float4*>(&g_t2[e1.x * 8 + q * 4]);
            acc.x = fmaf(m0, v0.x, acc.x); acc.y = fmaf(m0, v0.y, acc.y);
            acc.z = fmaf(m0, v0.z, acc.z); acc.w = fmaf(m0, v0.w, acc.w);
            acc.x = fmaf(m1, v1.x, acc.x); acc.y = fmaf(m1, v1.y, acc.y);
            acc.z = fmaf(m1, v1.z, acc.z); acc.w = fmaf(m1, v1.w, acc.w);
        }
        if (e < end) {
            int2 e0 = g_edge[e];
            float m = __int_as_float(e0.y);
            float4 v = *reinterpret_cast<const float4*>(&g_t2[e0.x * 8 + q * 4]);
            acc.x = fmaf(m, v.x, acc.x); acc.y = fmaf(m, v.y, acc.y);
            acc.z = fmaf(m, v.z, acc.z); acc.w = fmaf(m, v.w, acc.w);
        }
        float dis = g_dis[node];
        float d2 = dis * dis;
        float4 h = *reinterpret_cast<const float4*>(&g_t2[node * 8 + q * 4]);
        acc.x += d2 * h.x + sC[q * 4 + 0];
        acc.y += d2 * h.y + sC[q * 4 + 1];
        acc.z += d2 * h.z + sC[q * 4 + 2];
        acc.w += d2 * h.w + sC[q * 4 + 3];
    }
    float4 o;
    o.x = __shfl_xor_sync(0xFFFFFFFFu, acc.x, 1);
    o.y = __shfl_xor_sync(0xFFFFFFFFu, acc.y, 1);
    o.z = __shfl_xor_sync(0xFFFFFFFFu, acc.z, 1);
    o.w = __shfl_xor_sync(0xFFFFFFFFu, acc.w, 1);
    if (node < n && q == 0) {
        float a[8] = {acc.x, acc.y, acc.z, acc.w, o.x, o.y, o.z, o.w};
        float l[5];
        float m = -1e30f;
        #pragma unroll
        for (int c = 0; c < 5; ++c) {
            float s = 0.0f;
            #pragma unroll
            for (int r = 0; r < 8; ++r)
                s = fmaf(a[r], sB2[r * 5 + c], s);
            l[c] = s * 0.125f;
            m = fmaxf(m, l[c]);
        }
        float se = 0.0f;
        #pragma unroll
        for (int c = 0; c < 5; ++c) se += expf(l[c] - m);
        float lse = m + logf(se);
        #pragma unroll
        for (int c = 0; c < 5; ++c)
            out[node * 5 + c] = l[c] - lse;
    }
}

// ---------------------------------------------------------------------------
extern "C" void kernel_launch(void* const* d_in, const int* in_sizes, int n_in,
                              void* d_out, int out_size) {
    const float* x    = (const float*)d_in[0];
    const int*   ei   = (const int*)  d_in[1];
    const int*   dom  = (const int*)  d_in[2];
    const float* emb  = (const float*)d_in[3];
    const float* W1   = (const float*)d_in[4];
    const float* b1   = (const float*)d_in[5];
    const float* A1   = (const float*)d_in[6];
    const float* B1   = (const float*)d_in[7];
    const float* W2   = (const float*)d_in[8];
    const float* b2   = (const float*)d_in[9];
    const float* A2   = (const float*)d_in[10];
    const float* B2   = (const float*)d_in[11];
    float* out = (float*)d_out;

    int N = in_sizes[2];
    int E = in_sizes[1] / 2;
    const int* src = ei;
    const int* dst = ei + E;

    int nb256  = (N + 255) / 256;
    int eb256  = (E + 255) / 256;
    int nbScan = (N + SCAN_B - 1) / SCAN_B;
    int nbAgg  = (N + 127) / 128;

    k_zero    <<<nb256, 256>>>(N);
    k_deg_embW<<<32 + eb256, 256>>>(dst, emb, W1, E);
    k_scan1   <<<nbScan, SCAN_B>>>(N);
    k_scan2   <<<1, 32>>>();
    k_scan3   <<<nbScan, SCAN_B>>>(N);
    k_scatter <<<eb256, 256>>>(src, dst, E);
    k_prep    <<<1, 1024>>>(W1, A1, b1, A2, b2);
    k_t1      <<<nb256, 256>>>(x, dom, N);
    k_agg1mid <<<nbAgg, 256>>>(B1, W2, A2, N);
    k_out     <<<nbAgg, 256>>>(B2, out, N);
}